// round 1
// baseline (speedup 1.0000x reference)
#include <cuda_runtime.h>
#include <math.h>

// ---------------- problem constants ----------------
#define Nn      32768
#define Ll      3000
#define PERG    64
#define NG      512          // Nn / PERG
#define DEGc    16
#define Ec      (Nn*DEGc)    // 524288
#define HIDc    128
#define OUT3c   64
#define REDc    146
#define FINc    4672         // 32*146
#define EPSf    1e-5f

// ---------------- device scratch (static, no allocs) ----------------
__device__ float g_deg[Nn];
__device__ float g_dinv[Nn];
__device__ float g_A[NG*64*64];                 // 8 MB: per-graph dense aggregation matrix
__device__ float g_h0[(size_t)Nn * FINc];       // 612 MB: conv output
__device__ float g_h1[(size_t)Nn * HIDc];       // 16 MB
__device__ float g_h2[(size_t)Nn * HIDc];       // 16 MB

// ---------------- degree / dinv ----------------
__global__ void k_deg_init() {
    int i = blockIdx.x * blockDim.x + threadIdx.x;
    if (i < Nn) g_deg[i] = 1.0f;   // self-loop weight
}

__global__ void k_deg_accum(const int* __restrict__ dst, const float* __restrict__ w) {
    int e = blockIdx.x * blockDim.x + threadIdx.x;
    if (e < Ec) atomicAdd(&g_deg[dst[e]], w[e]);
}

__global__ void k_dinv() {
    int i = blockIdx.x * blockDim.x + threadIdx.x;
    if (i < Nn) g_dinv[i] = rsqrtf(g_deg[i]);
}

// ---------------- per-graph aggregation matrix A (dst-row, src-col) ----------------
__global__ void __launch_bounds__(256) k_buildA(const int* __restrict__ src,
                                                const int* __restrict__ dst,
                                                const float* __restrict__ w) {
    __shared__ float sA[64*64];
    __shared__ float sdin[64];
    const int g = blockIdx.x, tid = threadIdx.x;
    for (int i = tid; i < 4096; i += 256) sA[i] = 0.f;
    if (tid < 64) sdin[tid] = g_dinv[g*64 + tid];
    __syncthreads();
    const int base = g * (PERG * DEGc);   // 1024 edges per graph, src-contiguous
    for (int e = tid; e < PERG*DEGc; e += 256) {
        int s = src[base + e] - g*64;
        int d = dst[base + e] - g*64;
        float v = sdin[s] * w[base + e] * sdin[d];
        atomicAdd(&sA[d*64 + s], v);
    }
    __syncthreads();
    if (tid < 64) { float di = sdin[tid]; sA[tid*64 + tid] += di*di; }  // self-loop term
    __syncthreads();
    for (int i = tid; i < 4096; i += 256) g_A[g*4096 + i] = sA[i];
}

// ---------------- Conv1d (32 filters, width 100, stride 20) + bias + relu ----------------
// One CTA per node. warp = p-slice (p = warp + 8j, j<19), lane = channel.
// t-loop vectorized float4: weights per-lane from smem (conflict-free phases),
// x per-p as broadcast float4. FFMA-bound.
__global__ void __launch_bounds__(256) k_conv(const float* __restrict__ x,
                                              const float* __restrict__ cw,
                                              const float* __restrict__ cb) {
    __shared__ float sbuf[6352];            // [0,3200): weights [c][t]; [3200,6352): x (padded)
    const int n    = blockIdx.x;
    const int tid  = threadIdx.x;
    const int lane = tid & 31;              // channel
    const int wrp  = tid >> 5;              // p-group base

    for (int i = tid; i < 3200; i += 256) sbuf[i] = cw[i];
    {
        const float4* x4 = reinterpret_cast<const float4*>(x + (size_t)n * Ll);
        float4* sx4 = reinterpret_cast<float4*>(sbuf + 3200);
        for (int i = tid; i < 750; i += 256) sx4[i] = x4[i];
        for (int i = 3000 + tid; i < 3152; i += 256) sbuf[3200 + i] = 0.f;  // pad for p>=146
    }
    __syncthreads();

    float acc[19];
#pragma unroll
    for (int j = 0; j < 19; j++) acc[j] = 0.f;

    const float4* sw4 = reinterpret_cast<const float4*>(sbuf + lane * 100);
    const float4* sx4 = reinterpret_cast<const float4*>(sbuf + 3200);

#pragma unroll 5
    for (int t4 = 0; t4 < 25; t4++) {
        float4 wv = sw4[t4];
#pragma unroll
        for (int j = 0; j < 19; j++) {
            // index (p*20 + 4*t4)/4 = p*5 + t4
            float4 xv = sx4[(wrp + 8*j) * 5 + t4];
            acc[j] = fmaf(wv.x, xv.x, acc[j]);
            acc[j] = fmaf(wv.y, xv.y, acc[j]);
            acc[j] = fmaf(wv.z, xv.z, acc[j]);
            acc[j] = fmaf(wv.w, xv.w, acc[j]);
        }
    }
    const float b = cb[lane];
    __syncthreads();                       // all smem reads done -> reuse sbuf as output stage
    float* sout = sbuf;                    // 4672 floats, layout [c][p]
#pragma unroll
    for (int j = 0; j < 19; j++) {
        int p = wrp + 8*j;
        if (p < REDc) sout[lane * REDc + p] = fmaxf(acc[j] + b, 0.f);
    }
    __syncthreads();
    float4* o4 = reinterpret_cast<float4*>(g_h0 + (size_t)n * FINc);
    const float4* so4 = reinterpret_cast<const float4*>(sout);
    for (int i = tid; i < FINc/4; i += 256) o4[i] = so4[i];
}

// ---------------- fused GCN layer: Z = H_g @ W ; Y = A_g @ Z ; BN+bias+relu ----------------
// One CTA per graph (BM = 64 rows = exactly one graph). FINAL fuses pool+FC+log_softmax.
template<int K, int COUT, bool FINAL>
__global__ void __launch_bounds__(256) k_layer(
    const float* __restrict__ Hin, const float* __restrict__ W,
    const float* __restrict__ bias,
    const float* __restrict__ gam, const float* __restrict__ bet,
    const float* __restrict__ mean, const float* __restrict__ var,
    float* __restrict__ Hout,
    const float* __restrict__ fcw, const float* __restrict__ fcb,
    float* __restrict__ out)
{
    extern __shared__ float sm[];
    constexpr int TN = COUT / 16;        // 8 or 4 cols per thread
    constexpr int AP = 36;               // As pitch (bank-conflict-free)
    constexpr int BP = COUT + 4;         // Bs / Zs pitch
    float* As = sm;                      // 64 x AP
    float* Bs = sm + 64*AP;              // 32 x BP

    const int tid = threadIdx.x;
    const int tx  = tid & 15;
    const int ty  = tid >> 4;
    const int g   = blockIdx.x;

    float acc[4][TN];
#pragma unroll
    for (int r = 0; r < 4; r++)
#pragma unroll
        for (int j = 0; j < TN; j++) acc[r][j] = 0.f;

    const float* Hg = Hin + (size_t)g * 64 * K;
    const int lr = tid >> 2;             // 0..63
    const int lc = (tid & 3) * 8;        // 0,8,16,24

    // -------- phase 1: Z = H_g @ W --------
    for (int k0 = 0; k0 < K; k0 += 32) {
        __syncthreads();
        {
            const float* hp = Hg + (size_t)lr * K + k0 + lc;
            float4 a0 = *reinterpret_cast<const float4*>(hp);
            float4 a1 = *reinterpret_cast<const float4*>(hp + 4);
            *reinterpret_cast<float4*>(As + lr*AP + lc)     = a0;
            *reinterpret_cast<float4*>(As + lr*AP + lc + 4) = a1;
        }
        constexpr int C4 = COUT / 4;
#pragma unroll
        for (int q = 0; q < COUT/32; q++) {
            int idx = tid + q*256;
            int rr  = idx / C4;
            int cc  = (idx % C4) * 4;
            *reinterpret_cast<float4*>(Bs + rr*BP + cc) =
                *reinterpret_cast<const float4*>(W + (size_t)(k0 + rr)*COUT + cc);
        }
        __syncthreads();
#pragma unroll 8
        for (int kk = 0; kk < 32; kk++) {
            float a[4];
#pragma unroll
            for (int r = 0; r < 4; r++) a[r] = As[(ty*4 + r)*AP + kk];
            float bb[TN];
#pragma unroll
            for (int q = 0; q < TN/4; q++)
                *reinterpret_cast<float4*>(bb + q*4) =
                    *reinterpret_cast<const float4*>(Bs + kk*BP + tx*TN + q*4);
#pragma unroll
            for (int r = 0; r < 4; r++)
#pragma unroll
                for (int j = 0; j < TN; j++)
                    acc[r][j] = fmaf(a[r], bb[j], acc[r][j]);
        }
    }

    // -------- stage Z to smem, load A_g --------
    __syncthreads();
    float* Ag = sm;                      // 64 x 65
    float* Zs = sm + 64*65;              // 64 x BP
#pragma unroll
    for (int r = 0; r < 4; r++)
#pragma unroll
        for (int q = 0; q < TN/4; q++)
            *reinterpret_cast<float4*>(Zs + (ty*4 + r)*BP + tx*TN + q*4) =
                *reinterpret_cast<float4*>(&acc[r][q*4]);
    for (int i = tid; i < 4096; i += 256)
        Ag[(i >> 6)*65 + (i & 63)] = g_A[g*4096 + i];
    __syncthreads();

    // -------- phase 2: Y = A_g @ Z --------
#pragma unroll
    for (int r = 0; r < 4; r++)
#pragma unroll
        for (int j = 0; j < TN; j++) acc[r][j] = 0.f;
#pragma unroll 4
    for (int k = 0; k < 64; k++) {
        float a[4];
#pragma unroll
        for (int r = 0; r < 4; r++) a[r] = Ag[(ty*4 + r)*65 + k];
        float zz[TN];
#pragma unroll
        for (int q = 0; q < TN/4; q++)
            *reinterpret_cast<float4*>(zz + q*4) =
                *reinterpret_cast<const float4*>(Zs + k*BP + tx*TN + q*4);
#pragma unroll
        for (int r = 0; r < 4; r++)
#pragma unroll
            for (int j = 0; j < TN; j++)
                acc[r][j] = fmaf(a[r], zz[j], acc[r][j]);
    }

    // -------- epilogue: bias + BN(eval) + relu --------
    float sc[TN], sh[TN];
#pragma unroll
    for (int j = 0; j < TN; j++) {
        int col = tx*TN + j;
        float s = gam[col] * rsqrtf(var[col] + EPSf);
        sc[j] = s;
        sh[j] = (bias[col] - mean[col]) * s + bet[col];
    }
#pragma unroll
    for (int r = 0; r < 4; r++)
#pragma unroll
        for (int j = 0; j < TN; j++)
            acc[r][j] = fmaxf(fmaf(acc[r][j], sc[j], sh[j]), 0.f);

    if (!FINAL) {
#pragma unroll
        for (int r = 0; r < 4; r++)
#pragma unroll
            for (int q = 0; q < TN/4; q++)
                *reinterpret_cast<float4*>(Hout + (size_t)(g*64 + ty*4 + r)*COUT + tx*TN + q*4) =
                    *reinterpret_cast<float4*>(&acc[r][q*4]);
    } else {
        // mean-pool over 64 nodes -> FC(64->2) -> log_softmax
        __syncthreads();
        float* Ys = sm;                  // 64 x 64 (COUT==64, TN==4)
#pragma unroll
        for (int r = 0; r < 4; r++)
#pragma unroll
            for (int j = 0; j < TN; j++)
                Ys[(ty*4 + r)*64 + tx*TN + j] = acc[r][j];
        __syncthreads();
        float* pooled = sm + 4096;
        if (tid < 64) {
            float s = 0.f;
#pragma unroll 8
            for (int i = 0; i < 64; i++) s += Ys[i*64 + tid];
            pooled[tid] = s * (1.0f / 64.0f);
        }
        __syncthreads();
        if (tid < 2) {
            float l = fcb[tid];
#pragma unroll 8
            for (int j = 0; j < 64; j++) l = fmaf(pooled[j], fcw[j*2 + tid], l);
            pooled[64 + tid] = l;
        }
        __syncthreads();
        if (tid == 0) {
            float l0 = pooled[64], l1 = pooled[65];
            float m  = fmaxf(l0, l1);
            float lse = m + logf(expf(l0 - m) + expf(l1 - m));
            out[g*2 + 0] = l0 - lse;
            out[g*2 + 1] = l1 - lse;
        }
    }
}

// ---------------- host launcher ----------------
extern "C" void kernel_launch(void* const* d_in, const int* in_sizes, int n_in,
                              void* d_out, int out_size) {
    const float* x   = (const float*)d_in[0];
    const int*   ei  = (const int*)  d_in[1];
    const float* ea  = (const float*)d_in[2];
    // d_in[3] = batch (graphs are contiguous 64-node blocks; unused)
    const float* cw  = (const float*)d_in[4];
    const float* cb  = (const float*)d_in[5];
    const float* W1  = (const float*)d_in[6];
    const float* b1  = (const float*)d_in[7];
    const float* W2  = (const float*)d_in[8];
    const float* b2  = (const float*)d_in[9];
    const float* W3  = (const float*)d_in[10];
    const float* b3  = (const float*)d_in[11];
    const float* g1  = (const float*)d_in[12];
    const float* be1 = (const float*)d_in[13];
    const float* m1  = (const float*)d_in[14];
    const float* v1  = (const float*)d_in[15];
    const float* g2  = (const float*)d_in[16];
    const float* be2 = (const float*)d_in[17];
    const float* m2  = (const float*)d_in[18];
    const float* v2  = (const float*)d_in[19];
    const float* g3  = (const float*)d_in[20];
    const float* be3 = (const float*)d_in[21];
    const float* m3  = (const float*)d_in[22];
    const float* v3  = (const float*)d_in[23];
    const float* fcw = (const float*)d_in[24];
    const float* fcb = (const float*)d_in[25];
    float* out = (float*)d_out;

    const int* srcp = ei;
    const int* dstp = ei + Ec;

    float *ph0, *ph1, *ph2;
    cudaGetSymbolAddress((void**)&ph0, g_h0);
    cudaGetSymbolAddress((void**)&ph1, g_h1);
    cudaGetSymbolAddress((void**)&ph2, g_h2);

    k_deg_init <<<(Nn + 255)/256, 256>>>();
    k_deg_accum<<<Ec/256,        256>>>(dstp, ea);
    k_dinv     <<<(Nn + 255)/256, 256>>>();
    k_buildA   <<<NG, 256>>>(srcp, dstp, ea);
    k_conv     <<<Nn, 256>>>(x, cw, cb);

    const int smem128 = (64*65 + 64*(HIDc + 4)) * 4;   // 50432 B
    const int smem64  = (64*65 + 64*(OUT3c + 4)) * 4;  // 34048 B
    cudaFuncSetAttribute((const void*)k_layer<FINc, 128, false>,
                         cudaFuncAttributeMaxDynamicSharedMemorySize, smem128);
    cudaFuncSetAttribute((const void*)k_layer<128, 128, false>,
                         cudaFuncAttributeMaxDynamicSharedMemorySize, smem128);

    k_layer<FINc, 128, false><<<NG, 256, smem128>>>(ph0, W1, b1, g1, be1, m1, v1,
                                                    ph1, nullptr, nullptr, nullptr);
    k_layer<128, 128, false><<<NG, 256, smem128>>>(ph1, W2, b2, g2, be2, m2, v2,
                                                   ph2, nullptr, nullptr, nullptr);
    k_layer<128, 64, true><<<NG, 256, smem64>>>(ph2, W3, b3, g3, be3, m3, v3,
                                                nullptr, fcw, fcb, out);
}

// round 3
// speedup vs baseline: 1.8702x; 1.8702x over previous
#include <cuda_runtime.h>
#include <math.h>
#include <stdint.h>

// ---------------- problem constants ----------------
#define Nn      32768
#define Ll      3000
#define PERG    64
#define NG      512          // Nn / PERG
#define DEGc    16
#define Ec      (Nn*DEGc)    // 524288
#define HIDc    128
#define OUT3c   64
#define REDc    146
#define FINc    4672         // 32*146
#define EPSf    1e-5f
#define TILES   146          // FINc / 32

// ---------------- device scratch (static, no allocs) ----------------
__device__ float g_deg[Nn];
__device__ float g_dinv[Nn];
__device__ float g_A[NG*64*64];                 // 8 MB
__device__ float g_h0[(size_t)Nn * FINc];       // 612 MB (tf32-rounded values)
__device__ float g_h1[(size_t)Nn * HIDc];       // 16 MB
__device__ float g_h2[(size_t)Nn * HIDc];       // 16 MB
__device__ float g_Wt[(size_t)HIDc * FINc];     // 2.4 MB: W1^T, tf32-rounded

// ---------------- helpers ----------------
__device__ __forceinline__ uint32_t smem_u32(const void* p) {
    uint32_t a;
    asm("{ .reg .u64 t; cvta.to.shared.u64 t, %1; cvt.u32.u64 %0, t; }" : "=r"(a) : "l"(p));
    return a;
}
__device__ __forceinline__ float tf32r(float x) {
    uint32_t u;
    asm("cvt.rna.tf32.f32 %0, %1;" : "=r"(u) : "f"(x));
    return __uint_as_float(u);
}
__device__ __forceinline__ void mma_tf32(float* d, const uint32_t* a, uint32_t b0, uint32_t b1) {
    asm volatile(
        "mma.sync.aligned.m16n8k8.row.col.f32.tf32.tf32.f32 "
        "{%0,%1,%2,%3}, {%4,%5,%6,%7}, {%8,%9}, {%0,%1,%2,%3};"
        : "+f"(d[0]), "+f"(d[1]), "+f"(d[2]), "+f"(d[3])
        : "r"(a[0]), "r"(a[1]), "r"(a[2]), "r"(a[3]), "r"(b0), "r"(b1));
}
__device__ __forceinline__ void cp16(uint32_t dst, const void* src) {
    asm volatile("cp.async.cg.shared.global [%0], [%1], 16;" :: "r"(dst), "l"(src));
}
#define CP_COMMIT() asm volatile("cp.async.commit_group;" ::: "memory")
#define CP_WAIT1()  asm volatile("cp.async.wait_group 1;" ::: "memory")

// ---------------- degree / dinv ----------------
__global__ void k_deg_init() {
    int i = blockIdx.x * blockDim.x + threadIdx.x;
    if (i < Nn) g_deg[i] = 1.0f;
}
__global__ void k_deg_accum(const int* __restrict__ dst, const float* __restrict__ w) {
    int e = blockIdx.x * blockDim.x + threadIdx.x;
    if (e < Ec) atomicAdd(&g_deg[dst[e]], w[e]);
}
__global__ void k_dinv() {
    int i = blockIdx.x * blockDim.x + threadIdx.x;
    if (i < Nn) g_dinv[i] = rsqrtf(g_deg[i]);
}

// ---------------- per-graph aggregation matrix ----------------
__global__ void __launch_bounds__(256) k_buildA(const int* __restrict__ src,
                                                const int* __restrict__ dst,
                                                const float* __restrict__ w) {
    __shared__ float sA[64*64];
    __shared__ float sdin[64];
    const int g = blockIdx.x, tid = threadIdx.x;
    for (int i = tid; i < 4096; i += 256) sA[i] = 0.f;
    if (tid < 64) sdin[tid] = g_dinv[g*64 + tid];
    __syncthreads();
    const int base = g * (PERG * DEGc);
    for (int e = tid; e < PERG*DEGc; e += 256) {
        int s = src[base + e] - g*64;
        int d = dst[base + e] - g*64;
        float v = sdin[s] * w[base + e] * sdin[d];
        atomicAdd(&sA[d*64 + s], v);
    }
    __syncthreads();
    if (tid < 64) { float di = sdin[tid]; sA[tid*64 + tid] += di*di; }
    __syncthreads();
    for (int i = tid; i < 4096; i += 256) g_A[g*4096 + i] = sA[i];
}

// ---------------- W1 transpose + tf32 round ----------------
__global__ void k_wt(const float* __restrict__ W) {
    __shared__ float t[32][33];
    int k0 = blockIdx.x * 32, n0 = blockIdx.y * 32;
    int tx = threadIdx.x, ty = threadIdx.y;           // 32 x 8
    for (int r = 0; r < 32; r += 8)
        t[ty + r][tx] = W[(size_t)(k0 + ty + r) * HIDc + n0 + tx];
    __syncthreads();
    for (int r = 0; r < 32; r += 8)
        g_Wt[(size_t)(n0 + ty + r) * FINc + k0 + tx] = tf32r(t[tx][ty + r]);
}

// ---------------- Conv1d + bias + relu (fp32, tf32-rounded output) ----------------
__global__ void __launch_bounds__(256) k_conv(const float* __restrict__ x,
                                              const float* __restrict__ cw,
                                              const float* __restrict__ cb) {
    __shared__ float sbuf[6352];
    const int n    = blockIdx.x;
    const int tid  = threadIdx.x;
    const int lane = tid & 31;
    const int wrp  = tid >> 5;

    for (int i = tid; i < 3200; i += 256) sbuf[i] = cw[i];
    {
        const float4* x4 = reinterpret_cast<const float4*>(x + (size_t)n * Ll);
        float4* sx4 = reinterpret_cast<float4*>(sbuf + 3200);
        for (int i = tid; i < 750; i += 256) sx4[i] = x4[i];
        for (int i = 3000 + tid; i < 3152; i += 256) sbuf[3200 + i] = 0.f;
    }
    __syncthreads();

    float acc[19];
#pragma unroll
    for (int j = 0; j < 19; j++) acc[j] = 0.f;

    const float4* sw4 = reinterpret_cast<const float4*>(sbuf + lane * 100);
    const float4* sx4 = reinterpret_cast<const float4*>(sbuf + 3200);

#pragma unroll 5
    for (int t4 = 0; t4 < 25; t4++) {
        float4 wv = sw4[t4];
#pragma unroll
        for (int j = 0; j < 19; j++) {
            float4 xv = sx4[(wrp + 8*j) * 5 + t4];
            acc[j] = fmaf(wv.x, xv.x, acc[j]);
            acc[j] = fmaf(wv.y, xv.y, acc[j]);
            acc[j] = fmaf(wv.z, xv.z, acc[j]);
            acc[j] = fmaf(wv.w, xv.w, acc[j]);
        }
    }
    const float b = cb[lane];
    __syncthreads();
    float* sout = sbuf;
#pragma unroll
    for (int j = 0; j < 19; j++) {
        int p = wrp + 8*j;
        if (p < REDc) sout[lane * REDc + p] = tf32r(fmaxf(acc[j] + b, 0.f));
    }
    __syncthreads();
    float4* o4 = reinterpret_cast<float4*>(g_h0 + (size_t)n * FINc);
    const float4* so4 = reinterpret_cast<const float4*>(sout);
    for (int i = tid; i < FINc/4; i += 256) o4[i] = so4[i];
}

// ---------------- layer1 via mma.sync tf32 ----------------
// CTA = 2 graphs (M=128 rows), N=128, K=4672. cp.async double-buffered
// K-tiles of 32. 8 warps as 4x2 grid, each warp 32x64 via m16n8k8 HMMA.
// Epilogue: Z->smem, fp32 Y = A_g @ Z, bias+BN+relu -> g_h1.
__global__ void __launch_bounds__(256, 2) k_layer1_mma(
    const float* __restrict__ bias,
    const float* __restrict__ gam, const float* __restrict__ bet,
    const float* __restrict__ mean, const float* __restrict__ var)
{
    extern __shared__ float smf[];
    const uint32_t sb = smem_u32(smf);
    const int tid  = threadIdx.x;
    const int b    = blockIdx.x;                 // graph pair
    const int warp = tid >> 5, lane = tid & 31;
    const int wm   = warp >> 1, wn = warp & 1;   // 4 x 2 warp grid
    const int gID  = lane >> 2, tig = lane & 3;

    const float* Ap = g_h0 + (size_t)b * 128 * FINc;
    const int lr = tid >> 3;                     // 0..31 (row base)
    const int lc = (tid & 7) * 4;                // 0..28 (col, float4)

    // stage stride: 128*36 floats A + 128*36 floats B = 9216 floats = 36864 B
    auto issue = [&](int i) {
        const int s = i & 1;
        const int k0 = i * 32;
        const uint32_t stb = sb + (uint32_t)s * 36864u;
#pragma unroll
        for (int q = 0; q < 4; q++) {
            int r = lr + q * 32;
            uint32_t o = (uint32_t)(r * 36 + lc) * 4u;
            cp16(stb + o,          Ap   + (size_t)r * FINc + k0 + lc);
            cp16(stb + 18432u + o, g_Wt + (size_t)r * FINc + k0 + lc);
        }
    };

    float acc[2][8][4];
#pragma unroll
    for (int mi = 0; mi < 2; mi++)
#pragma unroll
        for (int j = 0; j < 8; j++)
#pragma unroll
            for (int c = 0; c < 4; c++) acc[mi][j][c] = 0.f;

    issue(0); CP_COMMIT();
    issue(1); CP_COMMIT();

    for (int i = 0; i < TILES; i++) {
        CP_WAIT1();
        __syncthreads();
        const float* As = smf + (i & 1) * 9216;
        const float* Bs = As + 4608;
#pragma unroll
        for (int kk = 0; kk < 4; kk++) {
            const int k0 = kk * 8;
            uint32_t a[2][4];
#pragma unroll
            for (int mi = 0; mi < 2; mi++) {
                int row = wm*32 + mi*16 + gID;
                a[mi][0] = __float_as_uint(As[row*36     + k0 + tig]);
                a[mi][1] = __float_as_uint(As[(row+8)*36 + k0 + tig]);
                a[mi][2] = __float_as_uint(As[row*36     + k0 + tig + 4]);
                a[mi][3] = __float_as_uint(As[(row+8)*36 + k0 + tig + 4]);
            }
#pragma unroll
            for (int j = 0; j < 8; j++) {
                int n = wn*64 + j*8 + gID;
                uint32_t b0 = __float_as_uint(Bs[n*36 + k0 + tig]);
                uint32_t b1 = __float_as_uint(Bs[n*36 + k0 + tig + 4]);
                mma_tf32(acc[0][j], a[0], b0, b1);
                mma_tf32(acc[1][j], a[1], b0, b1);
            }
        }
        __syncthreads();
        if (i + 2 < TILES) issue(i + 2);
        CP_COMMIT();
    }

    // ---- stage Z (128 x 128, pitch 130) and A_g to smem ----
    __syncthreads();
    float* Zs = smf;                               // 128 x 130 = 16640 floats
    float* Ag = smf + 16640;                       // 2 x (64 x 65) = 8320 floats
#pragma unroll
    for (int mi = 0; mi < 2; mi++)
#pragma unroll
        for (int j = 0; j < 8; j++) {
            int row = wm*32 + mi*16 + gID;
            int col = wn*64 + j*8 + 2*tig;
            *reinterpret_cast<float2*>(Zs + row*130 + col) =
                make_float2(acc[mi][j][0], acc[mi][j][1]);
            *reinterpret_cast<float2*>(Zs + (row+8)*130 + col) =
                make_float2(acc[mi][j][2], acc[mi][j][3]);
        }
    {
        const float* gA = g_A + (size_t)(2*b) * 4096;
        for (int i2 = tid; i2 < 8192; i2 += 256) {
            int gg = i2 >> 12, rr = (i2 >> 6) & 63, cc = i2 & 63;
            Ag[gg*4160 + rr*65 + cc] = gA[(size_t)gg*4096 + rr*64 + cc];
        }
    }
    __syncthreads();

    // ---- Y = A_g @ Z, bias+BN+relu ----
    {
        const int gg = tid >> 7;
        const int t  = tid & 127;
        const int tx = t & 15;
        const int ty = t >> 4;
        float ac[8][8];
#pragma unroll
        for (int r = 0; r < 8; r++)
#pragma unroll
            for (int j = 0; j < 8; j++) ac[r][j] = 0.f;

        const float* Agg = Ag + gg * 4160;
        const float* Zg  = Zs + gg * 64 * 130;
#pragma unroll 4
        for (int k = 0; k < 64; k++) {
            float a[8], z[8];
#pragma unroll
            for (int r = 0; r < 8; r++) a[r] = Agg[(ty*8 + r)*65 + k];
#pragma unroll
            for (int j = 0; j < 8; j++) z[j] = Zg[k*130 + tx*8 + j];
#pragma unroll
            for (int r = 0; r < 8; r++)
#pragma unroll
                for (int j = 0; j < 8; j++)
                    ac[r][j] = fmaf(a[r], z[j], ac[r][j]);
        }
        float sc[8], sh[8];
#pragma unroll
        for (int j = 0; j < 8; j++) {
            int col = tx*8 + j;
            float s = gam[col] * rsqrtf(var[col] + EPSf);
            sc[j] = s;
            sh[j] = (bias[col] - mean[col]) * s + bet[col];
        }
#pragma unroll
        for (int r = 0; r < 8; r++) {
            float v[8];
#pragma unroll
            for (int j = 0; j < 8; j++)
                v[j] = fmaxf(fmaf(ac[r][j], sc[j], sh[j]), 0.f);
            float* dst = g_h1 + (size_t)(b*128 + gg*64 + ty*8 + r) * HIDc + tx*8;
            *reinterpret_cast<float4*>(dst)     = make_float4(v[0], v[1], v[2], v[3]);
            *reinterpret_cast<float4*>(dst + 4) = make_float4(v[4], v[5], v[6], v[7]);
        }
    }
}

// ---------------- fused GCN layer (fp32, layers 2 & 3) ----------------
template<int K, int COUT, bool FINAL>
__global__ void __launch_bounds__(256) k_layer(
    const float* __restrict__ Hin, const float* __restrict__ W,
    const float* __restrict__ bias,
    const float* __restrict__ gam, const float* __restrict__ bet,
    const float* __restrict__ mean, const float* __restrict__ var,
    float* __restrict__ Hout,
    const float* __restrict__ fcw, const float* __restrict__ fcb,
    float* __restrict__ out)
{
    extern __shared__ float sm[];
    constexpr int TN = COUT / 16;
    constexpr int AP = 36;
    constexpr int BP = COUT + 4;
    float* As = sm;
    float* Bs = sm + 64*AP;

    const int tid = threadIdx.x;
    const int tx  = tid & 15;
    const int ty  = tid >> 4;
    const int g   = blockIdx.x;

    float acc[4][TN];
#pragma unroll
    for (int r = 0; r < 4; r++)
#pragma unroll
        for (int j = 0; j < TN; j++) acc[r][j] = 0.f;

    const float* Hg = Hin + (size_t)g * 64 * K;
    const int lr = tid >> 2;
    const int lc = (tid & 3) * 8;

    for (int k0 = 0; k0 < K; k0 += 32) {
        __syncthreads();
        {
            const float* hp = Hg + (size_t)lr * K + k0 + lc;
            float4 a0 = *reinterpret_cast<const float4*>(hp);
            float4 a1 = *reinterpret_cast<const float4*>(hp + 4);
            *reinterpret_cast<float4*>(As + lr*AP + lc)     = a0;
            *reinterpret_cast<float4*>(As + lr*AP + lc + 4) = a1;
        }
        constexpr int C4 = COUT / 4;
#pragma unroll
        for (int q = 0; q < COUT/32; q++) {
            int idx = tid + q*256;
            int rr  = idx / C4;
            int cc  = (idx % C4) * 4;
            *reinterpret_cast<float4*>(Bs + rr*BP + cc) =
                *reinterpret_cast<const float4*>(W + (size_t)(k0 + rr)*COUT + cc);
        }
        __syncthreads();
#pragma unroll 8
        for (int kk = 0; kk < 32; kk++) {
            float a[4];
#pragma unroll
            for (int r = 0; r < 4; r++) a[r] = As[(ty*4 + r)*AP + kk];
            float bb[TN];
#pragma unroll
            for (int q = 0; q < TN/4; q++)
                *reinterpret_cast<float4*>(bb + q*4) =
                    *reinterpret_cast<const float4*>(Bs + kk*BP + tx*TN + q*4);
#pragma unroll
            for (int r = 0; r < 4; r++)
#pragma unroll
                for (int j = 0; j < TN; j++)
                    acc[r][j] = fmaf(a[r], bb[j], acc[r][j]);
        }
    }

    __syncthreads();
    float* Ag = sm;
    float* Zs = sm + 64*65;
#pragma unroll
    for (int r = 0; r < 4; r++)
#pragma unroll
        for (int q = 0; q < TN/4; q++)
            *reinterpret_cast<float4*>(Zs + (ty*4 + r)*BP + tx*TN + q*4) =
                *reinterpret_cast<float4*>(&acc[r][q*4]);
    for (int i = tid; i < 4096; i += 256)
        Ag[(i >> 6)*65 + (i & 63)] = g_A[g*4096 + i];
    __syncthreads();

#pragma unroll
    for (int r = 0; r < 4; r++)
#pragma unroll
        for (int j = 0; j < TN; j++) acc[r][j] = 0.f;
#pragma unroll 4
    for (int k = 0; k < 64; k++) {
        float a[4];
#pragma unroll
        for (int r = 0; r < 4; r++) a[r] = Ag[(ty*4 + r)*65 + k];
        float zz[TN];
#pragma unroll
        for (int q = 0; q < TN/4; q++)
            *reinterpret_cast<float4*>(zz + q*4) =
                *reinterpret_cast<const float4*>(Zs + k*BP + tx*TN + q*4);
#pragma unroll
        for (int r = 0; r < 4; r++)
#pragma unroll
            for (int j = 0; j < TN; j++)
                acc[r][j] = fmaf(a[r], zz[j], acc[r][j]);
    }

    float sc[TN], sh[TN];
#pragma unroll
    for (int j = 0; j < TN; j++) {
        int col = tx*TN + j;
        float s = gam[col] * rsqrtf(var[col] + EPSf);
        sc[j] = s;
        sh[j] = (bias[col] - mean[col]) * s + bet[col];
    }
#pragma unroll
    for (int r = 0; r < 4; r++)
#pragma unroll
        for (int j = 0; j < TN; j++)
            acc[r][j] = fmaxf(fmaf(acc[r][j], sc[j], sh[j]), 0.f);

    if (!FINAL) {
#pragma unroll
        for (int r = 0; r < 4; r++)
#pragma unroll
            for (int q = 0; q < TN/4; q++)
                *reinterpret_cast<float4*>(Hout + (size_t)(g*64 + ty*4 + r)*COUT + tx*TN + q*4) =
                    *reinterpret_cast<float4*>(&acc[r][q*4]);
    } else {
        __syncthreads();
        float* Ys = sm;
#pragma unroll
        for (int r = 0; r < 4; r++)
#pragma unroll
            for (int j = 0; j < TN; j++)
                Ys[(ty*4 + r)*64 + tx*TN + j] = acc[r][j];
        __syncthreads();
        float* pooled = sm + 4096;
        if (tid < 64) {
            float s = 0.f;
#pragma unroll 8
            for (int i = 0; i < 64; i++) s += Ys[i*64 + tid];
            pooled[tid] = s * (1.0f / 64.0f);
        }
        __syncthreads();
        if (tid < 2) {
            float l = fcb[tid];
#pragma unroll 8
            for (int j = 0; j < 64; j++) l = fmaf(pooled[j], fcw[j*2 + tid], l);
            pooled[64 + tid] = l;
        }
        __syncthreads();
        if (tid == 0) {
            float l0 = pooled[64], l1 = pooled[65];
            float m  = fmaxf(l0, l1);
            float lse = m + logf(expf(l0 - m) + expf(l1 - m));
            out[g*2 + 0] = l0 - lse;
            out[g*2 + 1] = l1 - lse;
        }
    }
}

// ---------------- host launcher ----------------
extern "C" void kernel_launch(void* const* d_in, const int* in_sizes, int n_in,
                              void* d_out, int out_size) {
    const float* x   = (const float*)d_in[0];
    const int*   ei  = (const int*)  d_in[1];
    const float* ea  = (const float*)d_in[2];
    const float* cw  = (const float*)d_in[4];
    const float* cb  = (const float*)d_in[5];
    const float* W1  = (const float*)d_in[6];
    const float* b1  = (const float*)d_in[7];
    const float* W2  = (const float*)d_in[8];
    const float* b2  = (const float*)d_in[9];
    const float* W3  = (const float*)d_in[10];
    const float* b3  = (const float*)d_in[11];
    const float* g1  = (const float*)d_in[12];
    const float* be1 = (const float*)d_in[13];
    const float* m1  = (const float*)d_in[14];
    const float* v1  = (const float*)d_in[15];
    const float* g2  = (const float*)d_in[16];
    const float* be2 = (const float*)d_in[17];
    const float* m2  = (const float*)d_in[18];
    const float* v2  = (const float*)d_in[19];
    const float* g3  = (const float*)d_in[20];
    const float* be3 = (const float*)d_in[21];
    const float* m3  = (const float*)d_in[22];
    const float* v3  = (const float*)d_in[23];
    const float* fcw = (const float*)d_in[24];
    const float* fcb = (const float*)d_in[25];
    float* out = (float*)d_out;

    const int* srcp = ei;
    const int* dstp = ei + Ec;

    float *ph1, *ph2;
    cudaGetSymbolAddress((void**)&ph1, g_h1);
    cudaGetSymbolAddress((void**)&ph2, g_h2);

    k_deg_init <<<(Nn + 255)/256, 256>>>();
    k_deg_accum<<<Ec/256,        256>>>(dstp, ea);
    k_dinv     <<<(Nn + 255)/256, 256>>>();
    k_buildA   <<<NG, 256>>>(srcp, dstp, ea);
    {
        dim3 tb(32, 8);
        dim3 gb(FINc/32, HIDc/32);
        k_wt<<<gb, tb>>>(W1);
    }
    k_conv     <<<Nn, 256>>>(x, cw, cb);

    // layer 1 on tensor cores (mma.sync tf32)
    const int smemL1 = (128*130 + 2*64*65) * 4;   // 99840 B
    cudaFuncSetAttribute((const void*)k_layer1_mma,
                         cudaFuncAttributeMaxDynamicSharedMemorySize, smemL1);
    k_layer1_mma<<<NG/2, 256, smemL1>>>(b1, g1, be1, m1, v1);

    const int smem128 = (64*65 + 64*(HIDc + 4)) * 4;   // 50432 B
    const int smem64  = (64*65 + 64*(OUT3c + 4)) * 4;  // 34048 B
    cudaFuncSetAttribute((const void*)k_layer<128, 128, false>,
                         cudaFuncAttributeMaxDynamicSharedMemorySize, smem128);

    k_layer<128, 128, false><<<NG, 256, smem128>>>(ph1, W2, b2, g2, be2, m2, v2,
                                                   ph2, nullptr, nullptr, nullptr);
    k_layer<128, 64, true><<<NG, 256, smem64>>>(ph2, W3, b3, g3, be3, m3, v3,
                                                nullptr, fcw, fcb, out);
}

// round 4
// speedup vs baseline: 3.8417x; 2.0542x over previous
#include <cuda_runtime.h>
#include <math.h>
#include <stdint.h>

// ---------------- problem constants ----------------
#define Nn      32768
#define Ll      3000
#define PERG    64
#define NG      512          // Nn / PERG
#define DEGc    16
#define Ec      (Nn*DEGc)    // 524288
#define HIDc    128
#define OUT3c   64
#define REDc    146
#define FINc    4672         // 32*146
#define EPSf    1e-5f
#define TILES   146          // FINc / 32

// ---------------- device scratch (static, no allocs) ----------------
__device__ float g_deg[Nn];
__device__ float g_dinv[Nn];
__device__ float g_A[NG*64*64];                 // 8 MB
__device__ float g_h0[(size_t)Nn * FINc];       // 612 MB (tf32-rounded values)
__device__ float g_h1[(size_t)Nn * HIDc];       // 16 MB
__device__ float g_h2[(size_t)Nn * HIDc];       // 16 MB
__device__ float g_Wt[(size_t)HIDc * FINc];     // 2.4 MB: W1^T, tf32-rounded
__device__ float g_Wc[32*108];                  // conv weights, tf32, padded pitch 108

// ---------------- helpers ----------------
__device__ __forceinline__ uint32_t smem_u32(const void* p) {
    uint32_t a;
    asm("{ .reg .u64 t; cvta.to.shared.u64 t, %1; cvt.u32.u64 %0, t; }" : "=r"(a) : "l"(p));
    return a;
}
__device__ __forceinline__ float tf32r(float x) {
    uint32_t u;
    asm("cvt.rna.tf32.f32 %0, %1;" : "=r"(u) : "f"(x));
    return __uint_as_float(u);
}
__device__ __forceinline__ void mma_tf32(float* d, const uint32_t* a, uint32_t b0, uint32_t b1) {
    asm volatile(
        "mma.sync.aligned.m16n8k8.row.col.f32.tf32.tf32.f32 "
        "{%0,%1,%2,%3}, {%4,%5,%6,%7}, {%8,%9}, {%0,%1,%2,%3};"
        : "+f"(d[0]), "+f"(d[1]), "+f"(d[2]), "+f"(d[3])
        : "r"(a[0]), "r"(a[1]), "r"(a[2]), "r"(a[3]), "r"(b0), "r"(b1));
}
__device__ __forceinline__ void cp16(uint32_t dst, const void* src) {
    asm volatile("cp.async.cg.shared.global [%0], [%1], 16;" :: "r"(dst), "l"(src));
}
#define CP_COMMIT() asm volatile("cp.async.commit_group;" ::: "memory")
#define CP_WAIT1()  asm volatile("cp.async.wait_group 1;" ::: "memory")

// ---------------- degree / dinv ----------------
__global__ void k_deg_init() {
    int i = blockIdx.x * blockDim.x + threadIdx.x;
    if (i < Nn) g_deg[i] = 1.0f;
}
__global__ void k_deg_accum(const int* __restrict__ dst, const float* __restrict__ w) {
    int e = blockIdx.x * blockDim.x + threadIdx.x;
    if (e < Ec) atomicAdd(&g_deg[dst[e]], w[e]);
}
__global__ void k_dinv() {
    int i = blockIdx.x * blockDim.x + threadIdx.x;
    if (i < Nn) g_dinv[i] = rsqrtf(g_deg[i]);
}

// ---------------- per-graph aggregation matrix ----------------
__global__ void __launch_bounds__(256) k_buildA(const int* __restrict__ src,
                                                const int* __restrict__ dst,
                                                const float* __restrict__ w) {
    __shared__ float sA[64*64];
    __shared__ float sdin[64];
    const int g = blockIdx.x, tid = threadIdx.x;
    for (int i = tid; i < 4096; i += 256) sA[i] = 0.f;
    if (tid < 64) sdin[tid] = g_dinv[g*64 + tid];
    __syncthreads();
    const int base = g * (PERG * DEGc);
    for (int e = tid; e < PERG*DEGc; e += 256) {
        int s = src[base + e] - g*64;
        int d = dst[base + e] - g*64;
        float v = sdin[s] * w[base + e] * sdin[d];
        atomicAdd(&sA[d*64 + s], v);
    }
    __syncthreads();
    if (tid < 64) { float di = sdin[tid]; sA[tid*64 + tid] += di*di; }
    __syncthreads();
    for (int i = tid; i < 4096; i += 256) g_A[g*4096 + i] = sA[i];
}

// ---------------- W1 transpose + tf32 round ----------------
__global__ void k_wt(const float* __restrict__ W) {
    __shared__ float t[32][33];
    int k0 = blockIdx.x * 32, n0 = blockIdx.y * 32;
    int tx = threadIdx.x, ty = threadIdx.y;           // 32 x 8
    for (int r = 0; r < 32; r += 8)
        t[ty + r][tx] = W[(size_t)(k0 + ty + r) * HIDc + n0 + tx];
    __syncthreads();
    for (int r = 0; r < 32; r += 8)
        g_Wt[(size_t)(n0 + ty + r) * FINc + k0 + tx] = tf32r(t[tx][ty + r]);
}

// ---------------- conv weight prep: tf32, pitch 108, zero pad ----------------
__global__ void k_wc(const float* __restrict__ cw) {
    int i = blockIdx.x * blockDim.x + threadIdx.x;
    if (i < 32*108) {
        int c = i / 108, t = i % 108;
        g_Wc[i] = (t < 100) ? tf32r(cw[c*100 + t]) : 0.f;
    }
}

// ---------------- Conv1d via mma.sync tf32 ----------------
// One CTA (128 thr, 4 warps) per node. GEMM: M=32 (filters, 2 m16 tiles),
// N=160 p-positions (warp = 5 n8 tiles = 40 p's), K=104 (13 k8 steps).
// B fragment = implicit im2col: B[k=t][n=p] = xs[20p + t].
__global__ void __launch_bounds__(128) k_conv_tc(const float* __restrict__ x,
                                                 const float* __restrict__ cb) {
    __shared__ float sbuf[6740];   // [0,3284) x padded ; [3284,6740) weights pitch 108
    float* xs = sbuf;
    float* ws = sbuf + 3284;
    const int n    = blockIdx.x;
    const int tid  = threadIdx.x;
    const int warp = tid >> 5, lane = tid & 31;
    const int gID  = lane >> 2, tig = lane & 3;

    {
        const float4* x4 = reinterpret_cast<const float4*>(x + (size_t)n * Ll);
        float4* xs4 = reinterpret_cast<float4*>(xs);
        for (int i = tid; i < 750; i += 128) xs4[i] = x4[i];
        for (int i = 3000 + tid; i < 3284; i += 128) xs[i] = 0.f;
        const float4* w4 = reinterpret_cast<const float4*>(g_Wc);
        float4* ws4 = reinterpret_cast<float4*>(ws);
        for (int i = tid; i < 864; i += 128) ws4[i] = w4[i];
    }
    __syncthreads();

    float acc[2][5][4];
#pragma unroll
    for (int mi = 0; mi < 2; mi++)
#pragma unroll
        for (int nt = 0; nt < 5; nt++)
#pragma unroll
            for (int c = 0; c < 4; c++) acc[mi][nt][c] = 0.f;

    const int pbase = warp * 40;
#pragma unroll
    for (int k8 = 0; k8 < 13; k8++) {
        const int k0 = k8 * 8;
        uint32_t a[2][4];
#pragma unroll
        for (int mi = 0; mi < 2; mi++) {
            const int c = mi*16 + gID;
            a[mi][0] = __float_as_uint(ws[c*108 + k0 + tig]);
            a[mi][1] = __float_as_uint(ws[(c+8)*108 + k0 + tig]);
            a[mi][2] = __float_as_uint(ws[c*108 + k0 + tig + 4]);
            a[mi][3] = __float_as_uint(ws[(c+8)*108 + k0 + tig + 4]);
        }
#pragma unroll
        for (int nt = 0; nt < 5; nt++) {
            const int p = pbase + nt*8 + gID;
            uint32_t b0 = __float_as_uint(xs[20*p + k0 + tig]);
            uint32_t b1 = __float_as_uint(xs[20*p + k0 + tig + 4]);
            mma_tf32(acc[0][nt], a[0], b0, b1);
            mma_tf32(acc[1][nt], a[1], b0, b1);
        }
    }

    // bias per thread's 4 filter rows
    float bc[2][2];
#pragma unroll
    for (int mi = 0; mi < 2; mi++) {
        bc[mi][0] = cb[mi*16 + gID];
        bc[mi][1] = cb[mi*16 + gID + 8];
    }
    __syncthreads();                       // smem reads done; reuse as output stage
    float* sout = sbuf;                    // 4672 floats, layout [c][p]
#pragma unroll
    for (int mi = 0; mi < 2; mi++)
#pragma unroll
        for (int nt = 0; nt < 5; nt++) {
            const int c0 = mi*16 + gID, c1 = c0 + 8;
            const int p0 = pbase + nt*8 + 2*tig;
            if (p0 < REDc) {
                sout[c0*REDc + p0] = tf32r(fmaxf(acc[mi][nt][0] + bc[mi][0], 0.f));
                sout[c1*REDc + p0] = tf32r(fmaxf(acc[mi][nt][2] + bc[mi][1], 0.f));
            }
            if (p0 + 1 < REDc) {
                sout[c0*REDc + p0+1] = tf32r(fmaxf(acc[mi][nt][1] + bc[mi][0], 0.f));
                sout[c1*REDc + p0+1] = tf32r(fmaxf(acc[mi][nt][3] + bc[mi][1], 0.f));
            }
        }
    __syncthreads();
    float4* o4 = reinterpret_cast<float4*>(g_h0 + (size_t)n * FINc);
    const float4* so4 = reinterpret_cast<const float4*>(sout);
    for (int i = tid; i < FINc/4; i += 128) o4[i] = so4[i];
}

// ---------------- layer1 via mma.sync tf32 ----------------
__global__ void __launch_bounds__(256, 2) k_layer1_mma(
    const float* __restrict__ bias,
    const float* __restrict__ gam, const float* __restrict__ bet,
    const float* __restrict__ mean, const float* __restrict__ var)
{
    extern __shared__ float smf[];
    const uint32_t sb = smem_u32(smf);
    const int tid  = threadIdx.x;
    const int b    = blockIdx.x;                 // graph pair
    const int warp = tid >> 5, lane = tid & 31;
    const int wm   = warp >> 1, wn = warp & 1;   // 4 x 2 warp grid
    const int gID  = lane >> 2, tig = lane & 3;

    const float* Ap = g_h0 + (size_t)b * 128 * FINc;
    const int lr = tid >> 3;                     // 0..31
    const int lc = (tid & 7) * 4;                // 0..28

    auto issue = [&](int i) {
        const int s = i & 1;
        const int k0 = i * 32;
        const uint32_t stb = sb + (uint32_t)s * 36864u;
#pragma unroll
        for (int q = 0; q < 4; q++) {
            int r = lr + q * 32;
            uint32_t o = (uint32_t)(r * 36 + lc) * 4u;
            cp16(stb + o,          Ap   + (size_t)r * FINc + k0 + lc);
            cp16(stb + 18432u + o, g_Wt + (size_t)r * FINc + k0 + lc);
        }
    };

    float acc[2][8][4];
#pragma unroll
    for (int mi = 0; mi < 2; mi++)
#pragma unroll
        for (int j = 0; j < 8; j++)
#pragma unroll
            for (int c = 0; c < 4; c++) acc[mi][j][c] = 0.f;

    issue(0); CP_COMMIT();
    issue(1); CP_COMMIT();

    for (int i = 0; i < TILES; i++) {
        CP_WAIT1();
        __syncthreads();
        const float* As = smf + (i & 1) * 9216;
        const float* Bs = As + 4608;
#pragma unroll
        for (int kk = 0; kk < 4; kk++) {
            const int k0 = kk * 8;
            uint32_t a[2][4];
#pragma unroll
            for (int mi = 0; mi < 2; mi++) {
                int row = wm*32 + mi*16 + gID;
                a[mi][0] = __float_as_uint(As[row*36     + k0 + tig]);
                a[mi][1] = __float_as_uint(As[(row+8)*36 + k0 + tig]);
                a[mi][2] = __float_as_uint(As[row*36     + k0 + tig + 4]);
                a[mi][3] = __float_as_uint(As[(row+8)*36 + k0 + tig + 4]);
            }
#pragma unroll
            for (int j = 0; j < 8; j++) {
                int n = wn*64 + j*8 + gID;
                uint32_t b0 = __float_as_uint(Bs[n*36 + k0 + tig]);
                uint32_t b1 = __float_as_uint(Bs[n*36 + k0 + tig + 4]);
                mma_tf32(acc[0][j], a[0], b0, b1);
                mma_tf32(acc[1][j], a[1], b0, b1);
            }
        }
        __syncthreads();
        if (i + 2 < TILES) issue(i + 2);
        CP_COMMIT();
    }

    __syncthreads();
    float* Zs = smf;                               // 128 x 130
    float* Ag = smf + 16640;                       // 2 x (64 x 65)
#pragma unroll
    for (int mi = 0; mi < 2; mi++)
#pragma unroll
        for (int j = 0; j < 8; j++) {
            int row = wm*32 + mi*16 + gID;
            int col = wn*64 + j*8 + 2*tig;
            *reinterpret_cast<float2*>(Zs + row*130 + col) =
                make_float2(acc[mi][j][0], acc[mi][j][1]);
            *reinterpret_cast<float2*>(Zs + (row+8)*130 + col) =
                make_float2(acc[mi][j][2], acc[mi][j][3]);
        }
    {
        const float* gA = g_A + (size_t)(2*b) * 4096;
        for (int i2 = tid; i2 < 8192; i2 += 256) {
            int gg = i2 >> 12, rr = (i2 >> 6) & 63, cc = i2 & 63;
            Ag[gg*4160 + rr*65 + cc] = gA[(size_t)gg*4096 + rr*64 + cc];
        }
    }
    __syncthreads();

    {
        const int gg = tid >> 7;
        const int t  = tid & 127;
        const int tx = t & 15;
        const int ty = t >> 4;
        float ac[8][8];
#pragma unroll
        for (int r = 0; r < 8; r++)
#pragma unroll
            for (int j = 0; j < 8; j++) ac[r][j] = 0.f;

        const float* Agg = Ag + gg * 4160;
        const float* Zg  = Zs + gg * 64 * 130;
#pragma unroll 4
        for (int k = 0; k < 64; k++) {
            float a[8], z[8];
#pragma unroll
            for (int r = 0; r < 8; r++) a[r] = Agg[(ty*8 + r)*65 + k];
#pragma unroll
            for (int j = 0; j < 8; j++) z[j] = Zg[k*130 + tx*8 + j];
#pragma unroll
            for (int r = 0; r < 8; r++)
#pragma unroll
                for (int j = 0; j < 8; j++)
                    ac[r][j] = fmaf(a[r], z[j], ac[r][j]);
        }
        float sc[8], sh[8];
#pragma unroll
        for (int j = 0; j < 8; j++) {
            int col = tx*8 + j;
            float s = gam[col] * rsqrtf(var[col] + EPSf);
            sc[j] = s;
            sh[j] = (bias[col] - mean[col]) * s + bet[col];
        }
#pragma unroll
        for (int r = 0; r < 8; r++) {
            float v[8];
#pragma unroll
            for (int j = 0; j < 8; j++)
                v[j] = fmaxf(fmaf(ac[r][j], sc[j], sh[j]), 0.f);
            float* dst = g_h1 + (size_t)(b*128 + gg*64 + ty*8 + r) * HIDc + tx*8;
            *reinterpret_cast<float4*>(dst)     = make_float4(v[0], v[1], v[2], v[3]);
            *reinterpret_cast<float4*>(dst + 4) = make_float4(v[4], v[5], v[6], v[7]);
        }
    }
}

// ---------------- fused GCN layer (fp32, layers 2 & 3) ----------------
template<int K, int COUT, bool FINAL>
__global__ void __launch_bounds__(256) k_layer(
    const float* __restrict__ Hin, const float* __restrict__ W,
    const float* __restrict__ bias,
    const float* __restrict__ gam, const float* __restrict__ bet,
    const float* __restrict__ mean, const float* __restrict__ var,
    float* __restrict__ Hout,
    const float* __restrict__ fcw, const float* __restrict__ fcb,
    float* __restrict__ out)
{
    extern __shared__ float sm[];
    constexpr int TN = COUT / 16;
    constexpr int AP = 36;
    constexpr int BP = COUT + 4;
    float* As = sm;
    float* Bs = sm + 64*AP;

    const int tid = threadIdx.x;
    const int tx  = tid & 15;
    const int ty  = tid >> 4;
    const int g   = blockIdx.x;

    float acc[4][TN];
#pragma unroll
    for (int r = 0; r < 4; r++)
#pragma unroll
        for (int j = 0; j < TN; j++) acc[r][j] = 0.f;

    const float* Hg = Hin + (size_t)g * 64 * K;
    const int lr = tid >> 2;
    const int lc = (tid & 3) * 8;

    for (int k0 = 0; k0 < K; k0 += 32) {
        __syncthreads();
        {
            const float* hp = Hg + (size_t)lr * K + k0 + lc;
            float4 a0 = *reinterpret_cast<const float4*>(hp);
            float4 a1 = *reinterpret_cast<const float4*>(hp + 4);
            *reinterpret_cast<float4*>(As + lr*AP + lc)     = a0;
            *reinterpret_cast<float4*>(As + lr*AP + lc + 4) = a1;
        }
        constexpr int C4 = COUT / 4;
#pragma unroll
        for (int q = 0; q < COUT/32; q++) {
            int idx = tid + q*256;
            int rr  = idx / C4;
            int cc  = (idx % C4) * 4;
            *reinterpret_cast<float4*>(Bs + rr*BP + cc) =
                *reinterpret_cast<const float4*>(W + (size_t)(k0 + rr)*COUT + cc);
        }
        __syncthreads();
#pragma unroll 8
        for (int kk = 0; kk < 32; kk++) {
            float a[4];
#pragma unroll
            for (int r = 0; r < 4; r++) a[r] = As[(ty*4 + r)*AP + kk];
            float bb[TN];
#pragma unroll
            for (int q = 0; q < TN/4; q++)
                *reinterpret_cast<float4*>(bb + q*4) =
                    *reinterpret_cast<const float4*>(Bs + kk*BP + tx*TN + q*4);
#pragma unroll
            for (int r = 0; r < 4; r++)
#pragma unroll
                for (int j = 0; j < TN; j++)
                    acc[r][j] = fmaf(a[r], bb[j], acc[r][j]);
        }
    }

    __syncthreads();
    float* Ag = sm;
    float* Zs = sm + 64*65;
#pragma unroll
    for (int r = 0; r < 4; r++)
#pragma unroll
        for (int q = 0; q < TN/4; q++)
            *reinterpret_cast<float4*>(Zs + (ty*4 + r)*BP + tx*TN + q*4) =
                *reinterpret_cast<float4*>(&acc[r][q*4]);
    for (int i = tid; i < 4096; i += 256)
        Ag[(i >> 6)*65 + (i & 63)] = g_A[g*4096 + i];
    __syncthreads();

#pragma unroll
    for (int r = 0; r < 4; r++)
#pragma unroll
        for (int j = 0; j < TN; j++) acc[r][j] = 0.f;
#pragma unroll 4
    for (int k = 0; k < 64; k++) {
        float a[4];
#pragma unroll
        for (int r = 0; r < 4; r++) a[r] = Ag[(ty*4 + r)*65 + k];
        float zz[TN];
#pragma unroll
        for (int q = 0; q < TN/4; q++)
            *reinterpret_cast<float4*>(zz + q*4) =
                *reinterpret_cast<const float4*>(Zs + k*BP + tx*TN + q*4);
#pragma unroll
        for (int r = 0; r < 4; r++)
#pragma unroll
            for (int j = 0; j < TN; j++)
                acc[r][j] = fmaf(a[r], zz[j], acc[r][j]);
    }

    float sc[TN], sh[TN];
#pragma unroll
    for (int j = 0; j < TN; j++) {
        int col = tx*TN + j;
        float s = gam[col] * rsqrtf(var[col] + EPSf);
        sc[j] = s;
        sh[j] = (bias[col] - mean[col]) * s + bet[col];
    }
#pragma unroll
    for (int r = 0; r < 4; r++)
#pragma unroll
        for (int j = 0; j < TN; j++)
            acc[r][j] = fmaxf(fmaf(acc[r][j], sc[j], sh[j]), 0.f);

    if (!FINAL) {
#pragma unroll
        for (int r = 0; r < 4; r++)
#pragma unroll
            for (int q = 0; q < TN/4; q++)
                *reinterpret_cast<float4*>(Hout + (size_t)(g*64 + ty*4 + r)*COUT + tx*TN + q*4) =
                    *reinterpret_cast<float4*>(&acc[r][q*4]);
    } else {
        __syncthreads();
        float* Ys = sm;
#pragma unroll
        for (int r = 0; r < 4; r++)
#pragma unroll
            for (int j = 0; j < TN; j++)
                Ys[(ty*4 + r)*64 + tx*TN + j] = acc[r][j];
        __syncthreads();
        float* pooled = sm + 4096;
        if (tid < 64) {
            float s = 0.f;
#pragma unroll 8
            for (int i = 0; i < 64; i++) s += Ys[i*64 + tid];
            pooled[tid] = s * (1.0f / 64.0f);
        }
        __syncthreads();
        if (tid < 2) {
            float l = fcb[tid];
#pragma unroll 8
            for (int j = 0; j < 64; j++) l = fmaf(pooled[j], fcw[j*2 + tid], l);
            pooled[64 + tid] = l;
        }
        __syncthreads();
        if (tid == 0) {
            float l0 = pooled[64], l1 = pooled[65];
            float m  = fmaxf(l0, l1);
            float lse = m + logf(expf(l0 - m) + expf(l1 - m));
            out[g*2 + 0] = l0 - lse;
            out[g*2 + 1] = l1 - lse;
        }
    }
}

// ---------------- host launcher ----------------
extern "C" void kernel_launch(void* const* d_in, const int* in_sizes, int n_in,
                              void* d_out, int out_size) {
    const float* x   = (const float*)d_in[0];
    const int*   ei  = (const int*)  d_in[1];
    const float* ea  = (const float*)d_in[2];
    const float* cw  = (const float*)d_in[4];
    const float* cb  = (const float*)d_in[5];
    const float* W1  = (const float*)d_in[6];
    const float* b1  = (const float*)d_in[7];
    const float* W2  = (const float*)d_in[8];
    const float* b2  = (const float*)d_in[9];
    const float* W3  = (const float*)d_in[10];
    const float* b3  = (const float*)d_in[11];
    const float* g1  = (const float*)d_in[12];
    const float* be1 = (const float*)d_in[13];
    const float* m1  = (const float*)d_in[14];
    const float* v1  = (const float*)d_in[15];
    const float* g2  = (const float*)d_in[16];
    const float* be2 = (const float*)d_in[17];
    const float* m2  = (const float*)d_in[18];
    const float* v2  = (const float*)d_in[19];
    const float* g3  = (const float*)d_in[20];
    const float* be3 = (const float*)d_in[21];
    const float* m3  = (const float*)d_in[22];
    const float* v3  = (const float*)d_in[23];
    const float* fcw = (const float*)d_in[24];
    const float* fcb = (const float*)d_in[25];
    float* out = (float*)d_out;

    const int* srcp = ei;
    const int* dstp = ei + Ec;

    float *ph1, *ph2;
    cudaGetSymbolAddress((void**)&ph1, g_h1);
    cudaGetSymbolAddress((void**)&ph2, g_h2);

    k_deg_init <<<(Nn + 255)/256, 256>>>();
    k_deg_accum<<<Ec/256,        256>>>(dstp, ea);
    k_dinv     <<<(Nn + 255)/256, 256>>>();
    k_buildA   <<<NG, 256>>>(srcp, dstp, ea);
    {
        dim3 tb(32, 8);
        dim3 gb(FINc/32, HIDc/32);
        k_wt<<<gb, tb>>>(W1);
    }
    k_wc<<<(32*108 + 255)/256, 256>>>(cw);
    k_conv_tc<<<Nn, 128>>>(x, cb);

    // layer 1 on tensor cores (mma.sync tf32)
    const int smemL1 = (128*130 + 2*64*65) * 4;   // 99840 B
    cudaFuncSetAttribute((const void*)k_layer1_mma,
                         cudaFuncAttributeMaxDynamicSharedMemorySize, smemL1);
    k_layer1_mma<<<NG/2, 256, smemL1>>>(b1, g1, be1, m1, v1);

    const int smem128 = (64*65 + 64*(HIDc + 4)) * 4;   // 50432 B
    const int smem64  = (64*65 + 64*(OUT3c + 4)) * 4;  // 34048 B
    cudaFuncSetAttribute((const void*)k_layer<128, 128, false>,
                         cudaFuncAttributeMaxDynamicSharedMemorySize, smem128);

    k_layer<128, 128, false><<<NG, 256, smem128>>>(ph1, W2, b2, g2, be2, m2, v2,
                                                   ph2, nullptr, nullptr, nullptr);
    k_layer<128, 64, true><<<NG, 256, smem64>>>(ph2, W3, b3, g3, be3, m3, v3,
                                                nullptr, fcw, fcb, out);
}